// round 1
// baseline (speedup 1.0000x reference)
#include <cuda_runtime.h>
#include <math.h>

#define D  128
#define BB 512
#define NN 512
#define BN (BB*NN)

// ---- scratch (static __device__ arrays; no runtime allocation) ----
__device__ float g_W1[D*D];              // Wk @ Wa1  (composite weight)
__device__ float g_crel[BB*D];           // rel @ Wa3 + b_att
__device__ float g_fkW[BN*D];            // key @ W1  (active rows only)
__device__ float g_u[BB*D];              // hop state
__device__ int   g_idx[BN];              // compacted active row indices
__device__ int   g_count;

__device__ __forceinline__ float lrelu(float x) { return x > 0.f ? x : 0.01f*x; }

// ---- block reductions (blockDim == 256) ----
__device__ __forceinline__ float block_sum(float v, float* scratch) {
    int lane = threadIdx.x & 31, w = threadIdx.x >> 5;
    #pragma unroll
    for (int o = 16; o > 0; o >>= 1) v += __shfl_down_sync(0xffffffffu, v, o);
    if (lane == 0) scratch[w] = v;
    __syncthreads();
    if (threadIdx.x < 8) {
        v = scratch[threadIdx.x];
        #pragma unroll
        for (int o = 4; o > 0; o >>= 1) v += __shfl_down_sync(0xffu, v, o, 8);
        if (threadIdx.x == 0) scratch[0] = v;
    }
    __syncthreads();
    float r = scratch[0];
    __syncthreads();
    return r;
}

__device__ __forceinline__ float block_max(float v, float* scratch) {
    int lane = threadIdx.x & 31, w = threadIdx.x >> 5;
    #pragma unroll
    for (int o = 16; o > 0; o >>= 1) v = fmaxf(v, __shfl_down_sync(0xffffffffu, v, o));
    if (lane == 0) scratch[w] = v;
    __syncthreads();
    if (threadIdx.x < 8) {
        v = scratch[threadIdx.x];
        #pragma unroll
        for (int o = 4; o > 0; o >>= 1) v = fmaxf(v, __shfl_down_sync(0xffu, v, o, 8));
        if (threadIdx.x == 0) scratch[0] = v;
    }
    __syncthreads();
    float r = scratch[0];
    __syncthreads();
    return r;
}

// ---- prep: W1 = Wk @ Wa1 ; crel = rel @ Wa3 + b_att ; zero g_count ----
// grid = D + BB blocks, 128 threads
__global__ void __launch_bounds__(128) prep_kernel(
    const float* __restrict__ Wk, const float* __restrict__ W_att,
    const float* __restrict__ b_att, const float* __restrict__ rel)
{
    int blk = blockIdx.x;
    int t = threadIdx.x;
    if (blk == 0 && t == 0) g_count = 0;
    __shared__ float row_s[D];
    if (blk < D) {
        int k = blk;
        row_s[t] = Wk[k*D + t];
        __syncthreads();
        float acc = 0.f;
        #pragma unroll 8
        for (int j = 0; j < D; j++) acc += row_s[j] * W_att[j*D + t];
        g_W1[k*D + t] = acc;
    } else {
        int b = blk - D;
        row_s[t] = rel[b*D + t];
        __syncthreads();
        float acc = b_att[t];
        #pragma unroll 8
        for (int j = 0; j < D; j++) acc += row_s[j] * W_att[(2*D + j)*D + t];
        g_crel[b*D + t] = acc;
    }
}

// ---- warp-aggregated compaction of active (mask!=0) rows ----
__global__ void __launch_bounds__(256) compact_kernel(const int* __restrict__ mask) {
    int r = blockIdx.x * 256 + threadIdx.x;
    bool act = (mask[r] != 0);
    unsigned bal = __ballot_sync(0xffffffffu, act);
    int lane = threadIdx.x & 31;
    int tot = __popc(bal);
    int base = 0;
    if (lane == 0 && tot) base = atomicAdd(&g_count, tot);
    base = __shfl_sync(0xffffffffu, base, 0);
    if (act) g_idx[base + __popc(bal & ((1u << lane) - 1u))] = r;
}

// ---- GEMM: fkW[row] = key[row] @ W1 for compacted active rows ----
// 128x128 output tile, K=128 fully in smem, 256 threads, 8x8 per thread
__global__ void __launch_bounds__(256) gemm_kernel(const float* __restrict__ key) {
    extern __shared__ float sh[];
    float* As = sh;            // [k][row] 128x128 (transposed)
    float* Bs = sh + D*D;      // [k][d]   128x128
    __shared__ int ridx[128];

    int cnt = g_count;
    int base = blockIdx.x * 128;
    if (base >= cnt) return;
    int tid = threadIdx.x;

    if (tid < 128) ridx[tid] = (base + tid < cnt) ? g_idx[base + tid] : -1;
    __syncthreads();

    // load W1 -> Bs
    for (int i = tid; i < D*D/4; i += 256)
        ((float4*)Bs)[i] = ((const float4*)g_W1)[i];

    // load A rows (2 threads per row, 64 k each), transpose into As[k][row]
    int r = tid & 127;
    int half = tid >> 7;
    int gr = ridx[r];
    const float* src = (gr >= 0) ? (key + (size_t)gr * D + half*64) : (const float*)0;
    #pragma unroll
    for (int kk = 0; kk < 64; kk += 4) {
        float4 v = src ? *(const float4*)(src + kk) : make_float4(0.f,0.f,0.f,0.f);
        int k = half*64 + kk;
        As[(k+0)*D + r] = v.x;
        As[(k+1)*D + r] = v.y;
        As[(k+2)*D + r] = v.z;
        As[(k+3)*D + r] = v.w;
    }
    __syncthreads();

    int tx = tid & 15, ty = tid >> 4;
    float acc[8][8];
    #pragma unroll
    for (int i = 0; i < 8; i++)
        #pragma unroll
        for (int j = 0; j < 8; j++) acc[i][j] = 0.f;

    const float* Ap = As + ty*8;
    const float* Bp = Bs + tx*8;
    #pragma unroll 2
    for (int k = 0; k < D; k++) {
        float4 a0 = *(const float4*)(Ap + k*D);
        float4 a1 = *(const float4*)(Ap + k*D + 4);
        float4 b0 = *(const float4*)(Bp + k*D);
        float4 b1 = *(const float4*)(Bp + k*D + 4);
        float av[8] = {a0.x,a0.y,a0.z,a0.w,a1.x,a1.y,a1.z,a1.w};
        float bv[8] = {b0.x,b0.y,b0.z,b0.w,b1.x,b1.y,b1.z,b1.w};
        #pragma unroll
        for (int i = 0; i < 8; i++)
            #pragma unroll
            for (int j = 0; j < 8; j++)
                acc[i][j] += av[i]*bv[j];
    }

    #pragma unroll
    for (int i = 0; i < 8; i++) {
        int g = ridx[ty*8 + i];
        if (g >= 0) {
            float* dst = g_fkW + (size_t)g * D + tx*8;
            *(float4*)dst       = make_float4(acc[i][0],acc[i][1],acc[i][2],acc[i][3]);
            *(float4*)(dst + 4) = make_float4(acc[i][4],acc[i][5],acc[i][6],acc[i][7]);
        }
    }
}

// ---- fused hop: c = u@Wa2 + crel ; att ; masked softmax ; o=(p@value)@Wv ;
//      u' = l2norm(lrelu(u@W_lin + b_lin) + o).  One block per batch row b. ----
__global__ void __launch_bounds__(256) hop_kernel(
    int hop,
    const float* __restrict__ e1,
    const float* __restrict__ value,
    const int*   __restrict__ mask,
    const float* __restrict__ W_att,
    const float* __restrict__ W_lin,
    const float* __restrict__ b_lin,
    const float* __restrict__ Wv,
    float* __restrict__ out)
{
    __shared__ __align__(16) float u_s[D];
    __shared__ __align__(16) float c_s[D];
    __shared__ float ub_s[D];
    __shared__ float att_s[NN];
    __shared__ float msk_s[NN];
    __shared__ float red_s[8*D];
    __shared__ float scratch[8];

    const float* u_in = (hop == 0) ? e1 : g_u;
    float* u_out = (hop == 2) ? out : g_u;

    int b = blockIdx.x;
    int tid = threadIdx.x;
    int lane = tid & 31, w = tid >> 5;

    if (tid < D) u_s[tid] = u_in[b*D + tid];
    for (int n = tid; n < NN; n += 256) msk_s[n] = (float)mask[b*NN + n];
    __syncthreads();

    // step 1: c_s (threads 0..127) and ub_s (threads 128..255)
    if (tid < D) {
        int d = tid;
        float c = g_crel[b*D + d];
        #pragma unroll 8
        for (int k = 0; k < D; k++) c += u_s[k] * W_att[(D + k)*D + d];
        c_s[d] = c;
    } else {
        int d = tid - D;
        float v = b_lin[d];
        #pragma unroll 8
        for (int k = 0; k < D; k++) v += u_s[k] * W_lin[k*D + d];
        ub_s[d] = lrelu(v);
    }
    __syncthreads();

    // att for masked rows is constant: sum_d lrelu(c[d])
    float att0 = block_sum(tid < D ? lrelu(c_s[tid]) : 0.f, scratch);

    // pass 1: att[n] = sum_d lrelu(fkW[b,n,d] + c[d]) for active n
    const float* fk_b = g_fkW + (size_t)b * NN * D;
    float4 cv = *(const float4*)&c_s[lane*4];
    for (int j = 0; j < NN/8; j += 2) {
        int n0 = j*8 + w, n1 = (j+1)*8 + w;
        bool a0 = (msk_s[n0] != 0.f), a1 = (msk_s[n1] != 0.f);
        float s0 = 0.f, s1 = 0.f;
        if (a0) {
            float4 v = *(const float4*)(fk_b + (size_t)n0*D + lane*4);
            s0 = lrelu(v.x+cv.x) + lrelu(v.y+cv.y) + lrelu(v.z+cv.z) + lrelu(v.w+cv.w);
        }
        if (a1) {
            float4 v = *(const float4*)(fk_b + (size_t)n1*D + lane*4);
            s1 = lrelu(v.x+cv.x) + lrelu(v.y+cv.y) + lrelu(v.z+cv.z) + lrelu(v.w+cv.w);
        }
        #pragma unroll
        for (int o = 16; o > 0; o >>= 1) {
            s0 += __shfl_down_sync(0xffffffffu, s0, o);
            s1 += __shfl_down_sync(0xffffffffu, s1, o);
        }
        if (lane == 0) {
            att_s[n0] = a0 ? s0 : att0;
            att_s[n1] = a1 ? s1 : att0;
        }
    }
    __syncthreads();

    // masked softmax (max over ALL n, e zeroed on mask)
    float mx = -1e30f;
    for (int n = tid; n < NN; n += 256) mx = fmaxf(mx, att_s[n]);
    mx = block_max(mx, scratch);

    float Sp = 0.f;
    for (int n = tid; n < NN; n += 256) {
        float e = (msk_s[n] != 0.f) ? expf(att_s[n] - mx) : 0.f;
        att_s[n] = e;
        Sp += e;
    }
    float S = block_sum(Sp, scratch) + 1e-5f;

    // pass 2: q[d] = sum_n e[n] * value[b,n,d]
    const float* v_b = value + (size_t)b * NN * D;
    float o0=0.f, o1=0.f, o2=0.f, o3=0.f;
    for (int j = 0; j < NN/8; j += 2) {
        int n0 = j*8 + w, n1 = (j+1)*8 + w;
        float e0 = att_s[n0], e1v = att_s[n1];
        if (e0 > 0.f) {
            float4 v = *(const float4*)(v_b + (size_t)n0*D + lane*4);
            o0 += e0*v.x; o1 += e0*v.y; o2 += e0*v.z; o3 += e0*v.w;
        }
        if (e1v > 0.f) {
            float4 v = *(const float4*)(v_b + (size_t)n1*D + lane*4);
            o0 += e1v*v.x; o1 += e1v*v.y; o2 += e1v*v.z; o3 += e1v*v.w;
        }
    }
    red_s[w*D + lane*4 + 0] = o0;
    red_s[w*D + lane*4 + 1] = o1;
    red_s[w*D + lane*4 + 2] = o2;
    red_s[w*D + lane*4 + 3] = o3;
    __syncthreads();

    if (tid < D) {
        float o = 0.f;
        #pragma unroll
        for (int ww = 0; ww < 8; ww++) o += red_s[ww*D + tid];
        c_s[tid] = o / S;          // reuse c_s as q = p @ value
    }
    __syncthreads();

    if (tid < D) {
        float ov = 0.f;
        #pragma unroll 8
        for (int k = 0; k < D; k++) ov += c_s[k] * Wv[k*D + tid];
        u_s[tid] = ub_s[tid] + ov;  // reuse u_s as pre-norm x
    }
    __syncthreads();

    float nrm2 = block_sum(tid < D ? u_s[tid]*u_s[tid] : 0.f, scratch);
    float norm = sqrtf(nrm2);
    if (tid < D) {
        float x = u_s[tid];
        u_out[b*D + tid] = (norm > 1e-12f) ? (x / norm) : (x * 1e12f);
    }
}

extern "C" void kernel_launch(void* const* d_in, const int* in_sizes, int n_in,
                              void* d_out, int out_size) {
    const float* e1    = (const float*)d_in[0];
    const float* rel   = (const float*)d_in[1];
    const float* key   = (const float*)d_in[2];
    const float* value = (const float*)d_in[3];
    const int*   mask  = (const int*)  d_in[4];
    const float* Wk    = (const float*)d_in[5];
    /* Wv */
    const float* Wv    = (const float*)d_in[6];
    const float* Wlin  = (const float*)d_in[7];
    const float* blin  = (const float*)d_in[8];
    const float* Watt  = (const float*)d_in[9];
    const float* batt  = (const float*)d_in[10];
    float* out = (float*)d_out;

    prep_kernel<<<D + BB, 128>>>(Wk, Watt, batt, rel);
    compact_kernel<<<BN/256, 256>>>(mask);

    cudaFuncSetAttribute(gemm_kernel, cudaFuncAttributeMaxDynamicSharedMemorySize,
                         2*D*D*(int)sizeof(float));
    gemm_kernel<<<BN/128, 256, 2*D*D*sizeof(float)>>>(key);

    for (int h = 0; h < 3; h++)
        hop_kernel<<<BB, 256>>>(h, e1, value, mask, Watt, Wlin, blin, Wv, out);
}

// round 2
// speedup vs baseline: 1.5074x; 1.5074x over previous
#include <cuda_runtime.h>
#include <cuda_bf16.h>
#include <math.h>

#define D  128
#define BB 512
#define NN 512
#define BN (BB*NN)
#define APAD 136   // padded bf16 elems per smem row (272B -> conflict-free)

// ---- scratch (static device arrays; no runtime allocation) ----
__device__ __align__(16) __nv_bfloat16 g_W1h[D*D];   // bf16 hi of (Wk@Wa1)^T  [d][k]
__device__ __align__(16) __nv_bfloat16 g_W1l[D*D];   // bf16 lo residual       [d][k]
__device__ float g_crel[BB*D];                       // rel @ Wa3 + b_att
__device__ float g_fkW[BN*D];                        // key @ W1 (active rows)
__device__ float g_u[BB*D];                          // hop state
__device__ int   g_idx[BN];                          // compacted active rows
__device__ int   g_count;

__device__ __forceinline__ float lrelu(float x) { return x > 0.f ? x : 0.01f*x; }

// ---- block reductions for blockDim == 512 (16 warps) ----
__device__ __forceinline__ float block_sum512(float v, float* scratch) {
    int lane = threadIdx.x & 31, w = threadIdx.x >> 5;
    #pragma unroll
    for (int o = 16; o > 0; o >>= 1) v += __shfl_down_sync(0xffffffffu, v, o);
    if (lane == 0) scratch[w] = v;
    __syncthreads();
    if (threadIdx.x < 16) {
        v = scratch[threadIdx.x];
        #pragma unroll
        for (int o = 8; o > 0; o >>= 1) v += __shfl_down_sync(0xffffu, v, o, 16);
        if (threadIdx.x == 0) scratch[0] = v;
    }
    __syncthreads();
    float r = scratch[0];
    __syncthreads();
    return r;
}

__device__ __forceinline__ float block_max512(float v, float* scratch) {
    int lane = threadIdx.x & 31, w = threadIdx.x >> 5;
    #pragma unroll
    for (int o = 16; o > 0; o >>= 1) v = fmaxf(v, __shfl_down_sync(0xffffffffu, v, o));
    if (lane == 0) scratch[w] = v;
    __syncthreads();
    if (threadIdx.x < 16) {
        v = scratch[threadIdx.x];
        #pragma unroll
        for (int o = 8; o > 0; o >>= 1) v = fmaxf(v, __shfl_down_sync(0xffffu, v, o, 16));
        if (threadIdx.x == 0) scratch[0] = v;
    }
    __syncthreads();
    float r = scratch[0];
    __syncthreads();
    return r;
}

// ---- prep: W1 = Wk @ Wa1 (split bf16, transposed) ; crel = rel@Wa3 + b_att ----
__global__ void __launch_bounds__(128) prep_kernel(
    const float* __restrict__ Wk, const float* __restrict__ W_att,
    const float* __restrict__ b_att, const float* __restrict__ rel)
{
    int blk = blockIdx.x;
    int t = threadIdx.x;
    if (blk == 0 && t == 0) g_count = 0;
    __shared__ float row_s[D];
    if (blk < D) {
        int k = blk;
        row_s[t] = Wk[k*D + t];
        __syncthreads();
        float acc = 0.f;
        #pragma unroll 8
        for (int j = 0; j < D; j++) acc += row_s[j] * W_att[j*D + t];
        __nv_bfloat16 hi = __float2bfloat16_rn(acc);
        __nv_bfloat16 lo = __float2bfloat16_rn(acc - __bfloat162float(hi));
        g_W1h[t*D + k] = hi;   // transposed: [d][k] for col-major B fragment
        g_W1l[t*D + k] = lo;
    } else {
        int b = blk - D;
        row_s[t] = rel[b*D + t];
        __syncthreads();
        float acc = b_att[t];
        #pragma unroll 8
        for (int j = 0; j < D; j++) acc += row_s[j] * W_att[(2*D + j)*D + t];
        g_crel[b*D + t] = acc;
    }
}

// ---- warp-aggregated compaction of active rows ----
__global__ void __launch_bounds__(256) compact_kernel(const int* __restrict__ mask) {
    int r = blockIdx.x * 256 + threadIdx.x;
    bool act = (mask[r] != 0);
    unsigned bal = __ballot_sync(0xffffffffu, act);
    int lane = threadIdx.x & 31;
    int tot = __popc(bal);
    int base = 0;
    if (lane == 0 && tot) base = atomicAdd(&g_count, tot);
    base = __shfl_sync(0xffffffffu, base, 0);
    if (act) g_idx[base + __popc(bal & ((1u << lane) - 1u))] = r;
}

// ---- tensor-core GEMM: fkW = key @ W1, error-compensated bf16 (3 products) ----
__device__ __forceinline__ void mma_bf16(float (&d)[4], const unsigned (&a)[4],
                                         const unsigned (&b)[2]) {
    asm volatile(
        "mma.sync.aligned.m16n8k16.row.col.f32.bf16.bf16.f32 "
        "{%0,%1,%2,%3}, {%4,%5,%6,%7}, {%8,%9}, {%0,%1,%2,%3};"
        : "+f"(d[0]), "+f"(d[1]), "+f"(d[2]), "+f"(d[3])
        : "r"(a[0]), "r"(a[1]), "r"(a[2]), "r"(a[3]), "r"(b[0]), "r"(b[1]));
}

__global__ void __launch_bounds__(256) gemm_kernel(const float* __restrict__ key) {
    extern __shared__ char sh[];
    __nv_bfloat16* Ah = (__nv_bfloat16*)sh;          // [128][APAD]
    __nv_bfloat16* Al = Ah + 128*APAD;
    __nv_bfloat16* Bh = Al + 128*APAD;               // [d][APAD]
    __nv_bfloat16* Bl = Bh + 128*APAD;
    __shared__ int ridx[128];

    int cnt = g_count;
    int base = blockIdx.x * 128;
    if (base >= cnt) return;
    int tid = threadIdx.x;

    if (tid < 128) ridx[tid] = (base + tid < cnt) ? g_idx[base + tid] : -1;
    __syncthreads();

    // B: copy split W1 (bf16) into padded smem
    {
        unsigned* dBh = (unsigned*)Bh;
        unsigned* dBl = (unsigned*)Bl;
        const unsigned* sBh = (const unsigned*)g_W1h;
        const unsigned* sBl = (const unsigned*)g_W1l;
        for (int i = tid; i < D*D/2; i += 256) {
            int d = i >> 6, kp = i & 63;           // 64 uint32 words per row
            dBh[d*(APAD/2) + kp] = sBh[i];
            dBl[d*(APAD/2) + kp] = sBl[i];
        }
    }
    // A: load fp32 key rows, split into hi/lo bf16
    {
        int r = tid & 127, half = tid >> 7;
        int gr = ridx[r];
        const float* src = (gr >= 0) ? key + (size_t)gr * D + half*64 : (const float*)0;
        #pragma unroll
        for (int c = 0; c < 64; c += 4) {
            float4 v = src ? *(const float4*)(src + c)
                           : make_float4(0.f, 0.f, 0.f, 0.f);
            int col = half*64 + c;
            __nv_bfloat16 h0 = __float2bfloat16_rn(v.x);
            __nv_bfloat16 h1 = __float2bfloat16_rn(v.y);
            __nv_bfloat16 h2 = __float2bfloat16_rn(v.z);
            __nv_bfloat16 h3 = __float2bfloat16_rn(v.w);
            __nv_bfloat16 l0 = __float2bfloat16_rn(v.x - __bfloat162float(h0));
            __nv_bfloat16 l1 = __float2bfloat16_rn(v.y - __bfloat162float(h1));
            __nv_bfloat16 l2 = __float2bfloat16_rn(v.z - __bfloat162float(h2));
            __nv_bfloat16 l3 = __float2bfloat16_rn(v.w - __bfloat162float(h3));
            __nv_bfloat162* ph = (__nv_bfloat162*)(Ah + r*APAD + col);
            __nv_bfloat162* pl = (__nv_bfloat162*)(Al + r*APAD + col);
            ph[0] = __nv_bfloat162(h0, h1); ph[1] = __nv_bfloat162(h2, h3);
            pl[0] = __nv_bfloat162(l0, l1); pl[1] = __nv_bfloat162(l2, l3);
        }
    }
    __syncthreads();

    int w = tid >> 5, lane = tid & 31;
    int wr = w >> 1;        // warp row group: rows [wr*32, wr*32+32)
    int wc = w & 1;         // warp col group: cols [wc*64, wc*64+64)
    int grp = lane >> 2, q = lane & 3;

    float acc[2][8][4];
    #pragma unroll
    for (int mt = 0; mt < 2; mt++)
        #pragma unroll
        for (int nt = 0; nt < 8; nt++)
            #pragma unroll
            for (int i = 0; i < 4; i++) acc[mt][nt][i] = 0.f;

    const unsigned* A32h = (const unsigned*)Ah;
    const unsigned* A32l = (const unsigned*)Al;
    const unsigned* B32h = (const unsigned*)Bh;
    const unsigned* B32l = (const unsigned*)Bl;
    const int RW = APAD/2;   // 68 words per row

    #pragma unroll
    for (int ks = 0; ks < 8; ks++) {
        int kw = ks*8 + q;     // word offset within row (k0/2 + q)
        unsigned ah[2][4], al[2][4];
        #pragma unroll
        for (int mt = 0; mt < 2; mt++) {
            int r0 = (wr*32 + mt*16 + grp) * RW;
            int r8 = r0 + 8*RW;
            ah[mt][0] = A32h[r0 + kw];
            ah[mt][1] = A32h[r8 + kw];
            ah[mt][2] = A32h[r0 + kw + 4];
            ah[mt][3] = A32h[r8 + kw + 4];
            al[mt][0] = A32l[r0 + kw];
            al[mt][1] = A32l[r8 + kw];
            al[mt][2] = A32l[r0 + kw + 4];
            al[mt][3] = A32l[r8 + kw + 4];
        }
        unsigned bh[8][2], bl[8][2];
        #pragma unroll
        for (int nt = 0; nt < 8; nt++) {
            int nr = (wc*64 + nt*8 + grp) * RW;
            bh[nt][0] = B32h[nr + kw];
            bh[nt][1] = B32h[nr + kw + 4];
            bl[nt][0] = B32l[nr + kw];
            bl[nt][1] = B32l[nr + kw + 4];
        }
        #pragma unroll
        for (int mt = 0; mt < 2; mt++)
            #pragma unroll
            for (int nt = 0; nt < 8; nt++) {
                mma_bf16(acc[mt][nt], ah[mt], bh[nt]);
                mma_bf16(acc[mt][nt], ah[mt], bl[nt]);
                mma_bf16(acc[mt][nt], al[mt], bh[nt]);
            }
    }

    #pragma unroll
    for (int mt = 0; mt < 2; mt++) {
        int row = wr*32 + mt*16 + grp;
        int g1 = ridx[row], g2 = ridx[row + 8];
        #pragma unroll
        for (int nt = 0; nt < 8; nt++) {
            int col = wc*64 + nt*8 + q*2;
            if (g1 >= 0)
                *(float2*)(g_fkW + (size_t)g1 * D + col) =
                    make_float2(acc[mt][nt][0], acc[mt][nt][1]);
            if (g2 >= 0)
                *(float2*)(g_fkW + (size_t)g2 * D + col) =
                    make_float2(acc[mt][nt][2], acc[mt][nt][3]);
        }
    }
}

// ---- fused hop: 512 threads per block, one block per batch row ----
__global__ void __launch_bounds__(512) hop_kernel(
    int hop,
    const float* __restrict__ e1,
    const float* __restrict__ value,
    const int*   __restrict__ mask,
    const float* __restrict__ W_att,
    const float* __restrict__ W_lin,
    const float* __restrict__ b_lin,
    const float* __restrict__ Wv,
    float* __restrict__ out)
{
    __shared__ __align__(16) float u_s[D];
    __shared__ __align__(16) float c_s[D];
    __shared__ float ub_s[D];
    __shared__ float att_s[NN];
    __shared__ float msk_s[NN];
    __shared__ float red_s[16*D];
    __shared__ float scratch[16];

    const float* u_in = (hop == 0) ? e1 : g_u;
    float* u_out = (hop == 2) ? out : g_u;

    int b = blockIdx.x;
    int tid = threadIdx.x;
    int lane = tid & 31, w = tid >> 5;   // 16 warps

    if (tid < D) u_s[tid] = u_in[b*D + tid];
    for (int n = tid; n < NN; n += 512) msk_s[n] = (float)mask[b*NN + n];
    __syncthreads();

    // c = u@Wa2 + crel (threads 0..127); ub = lrelu(u@W_lin + b_lin) (128..255)
    if (tid < D) {
        int d = tid;
        float c = g_crel[b*D + d];
        #pragma unroll 8
        for (int k = 0; k < D; k++) c += u_s[k] * W_att[(D + k)*D + d];
        c_s[d] = c;
    } else if (tid < 2*D) {
        int d = tid - D;
        float v = b_lin[d];
        #pragma unroll 8
        for (int k = 0; k < D; k++) v += u_s[k] * W_lin[k*D + d];
        ub_s[d] = lrelu(v);
    }
    __syncthreads();

    // masked-row attention logit is a per-b constant
    float att0 = block_sum512(tid < D ? lrelu(c_s[tid]) : 0.f, scratch);

    // pass 1: att[n] = sum_d lrelu(fkW[b,n,d] + c[d]) for active n
    const float* fk_b = g_fkW + (size_t)b * NN * D;
    float4 cv = *(const float4*)&c_s[lane*4];
    #pragma unroll
    for (int j = 0; j < 32; j += 4) {
        int   nn[4];
        bool  aa[4];
        float ss[4];
        #pragma unroll
        for (int i = 0; i < 4; i++) {
            nn[i] = (j + i)*16 + w;
            aa[i] = (msk_s[nn[i]] != 0.f);
            ss[i] = 0.f;
        }
        #pragma unroll
        for (int i = 0; i < 4; i++) if (aa[i]) {
            float4 v = *(const float4*)(fk_b + (size_t)nn[i]*D + lane*4);
            ss[i] = lrelu(v.x+cv.x) + lrelu(v.y+cv.y) + lrelu(v.z+cv.z) + lrelu(v.w+cv.w);
        }
        #pragma unroll
        for (int o = 16; o > 0; o >>= 1)
            #pragma unroll
            for (int i = 0; i < 4; i++)
                ss[i] += __shfl_down_sync(0xffffffffu, ss[i], o);
        if (lane == 0) {
            #pragma unroll
            for (int i = 0; i < 4; i++) att_s[nn[i]] = aa[i] ? ss[i] : att0;
        }
    }
    __syncthreads();

    // masked softmax (max over ALL n, e zeroed where masked)
    float mx = -1e30f;
    for (int n = tid; n < NN; n += 512) mx = fmaxf(mx, att_s[n]);
    mx = block_max512(mx, scratch);

    float Sp = 0.f;
    for (int n = tid; n < NN; n += 512) {
        float e = (msk_s[n] != 0.f) ? expf(att_s[n] - mx) : 0.f;
        att_s[n] = e;
        Sp += e;
    }
    float S = block_sum512(Sp, scratch) + 1e-5f;

    // pass 2: q[d] = sum_n e[n] * value[b,n,d]
    const float* v_b = value + (size_t)b * NN * D;
    float o0 = 0.f, o1 = 0.f, o2 = 0.f, o3 = 0.f;
    #pragma unroll
    for (int j = 0; j < 32; j += 4) {
        #pragma unroll
        for (int i = 0; i < 4; i++) {
            int n = (j + i)*16 + w;
            float e = att_s[n];
            if (e > 0.f) {
                float4 v = *(const float4*)(v_b + (size_t)n*D + lane*4);
                o0 += e*v.x; o1 += e*v.y; o2 += e*v.z; o3 += e*v.w;
            }
        }
    }
    red_s[w*D + lane*4 + 0] = o0;
    red_s[w*D + lane*4 + 1] = o1;
    red_s[w*D + lane*4 + 2] = o2;
    red_s[w*D + lane*4 + 3] = o3;
    __syncthreads();

    if (tid < D) {
        float o = 0.f;
        #pragma unroll
        for (int ww = 0; ww < 16; ww++) o += red_s[ww*D + tid];
        c_s[tid] = o / S;          // reuse c_s as q = p @ value
    }
    __syncthreads();

    if (tid < D) {
        float ov = 0.f;
        #pragma unroll 8
        for (int k = 0; k < D; k++) ov += c_s[k] * Wv[k*D + tid];
        u_s[tid] = ub_s[tid] + ov;  // pre-norm x
    }
    __syncthreads();

    float nrm2 = block_sum512(tid < D ? u_s[tid]*u_s[tid] : 0.f, scratch);
    float norm = sqrtf(nrm2);
    if (tid < D) {
        float x = u_s[tid];
        u_out[b*D + tid] = (norm > 1e-12f) ? (x / norm) : (x * 1e12f);
    }
}

extern "C" void kernel_launch(void* const* d_in, const int* in_sizes, int n_in,
                              void* d_out, int out_size) {
    const float* e1    = (const float*)d_in[0];
    const float* rel   = (const float*)d_in[1];
    const float* key   = (const float*)d_in[2];
    const float* value = (const float*)d_in[3];
    const int*   mask  = (const int*)  d_in[4];
    const float* Wk    = (const float*)d_in[5];
    const float* Wv    = (const float*)d_in[6];
    const float* Wlin  = (const float*)d_in[7];
    const float* blin  = (const float*)d_in[8];
    const float* Watt  = (const float*)d_in[9];
    const float* batt  = (const float*)d_in[10];
    float* out = (float*)d_out;

    prep_kernel<<<D + BB, 128>>>(Wk, Watt, batt, rel);
    compact_kernel<<<BN/256, 256>>>(mask);

    int gemm_smem = 4 * 128 * APAD * (int)sizeof(__nv_bfloat16);
    cudaFuncSetAttribute(gemm_kernel, cudaFuncAttributeMaxDynamicSharedMemorySize,
                         gemm_smem);
    gemm_kernel<<<BN/128, 256, gemm_smem>>>(key);

    for (int h = 0; h < 3; h++)
        hop_kernel<<<BB, 512>>>(h, e1, value, mask, Watt, Wlin, blin, Wv, out);
}

// round 3
// speedup vs baseline: 1.5517x; 1.0294x over previous
#include <cuda_runtime.h>
#include <cuda_bf16.h>
#include <math.h>

#define D  128
#define BB 512
#define NN 512
#define BN (BB*NN)
#define APAD 136   // padded bf16 elems per smem row (272B; 272 mod 128 = 16 -> LDSM conflict-free)

// ---- scratch (static device arrays; no runtime allocation) ----
__device__ __align__(16) __nv_bfloat16 g_W1h[D*D];   // bf16 hi of (Wk@Wa1)^T  [d][k]
__device__ __align__(16) __nv_bfloat16 g_W1l[D*D];   // bf16 lo residual       [d][k]
__device__ float g_crel[BB*D];                       // rel @ Wa3 + b_att
__device__ float g_fkW[BN*D];                        // key @ W1 (active rows)
__device__ float g_u[BB*D];                          // hop state
__device__ int   g_idx[BN];                          // compacted active rows
__device__ int   g_count;

__device__ __forceinline__ float lrelu(float x) { return x > 0.f ? x : 0.01f*x; }

// ---- block reductions for blockDim == 512 (16 warps) ----
__device__ __forceinline__ float block_sum512(float v, float* scratch) {
    int lane = threadIdx.x & 31, w = threadIdx.x >> 5;
    #pragma unroll
    for (int o = 16; o > 0; o >>= 1) v += __shfl_down_sync(0xffffffffu, v, o);
    if (lane == 0) scratch[w] = v;
    __syncthreads();
    if (threadIdx.x < 16) {
        v = scratch[threadIdx.x];
        #pragma unroll
        for (int o = 8; o > 0; o >>= 1) v += __shfl_down_sync(0xffffu, v, o, 16);
        if (threadIdx.x == 0) scratch[0] = v;
    }
    __syncthreads();
    float r = scratch[0];
    __syncthreads();
    return r;
}

__device__ __forceinline__ float block_max512(float v, float* scratch) {
    int lane = threadIdx.x & 31, w = threadIdx.x >> 5;
    #pragma unroll
    for (int o = 16; o > 0; o >>= 1) v = fmaxf(v, __shfl_down_sync(0xffffffffu, v, o));
    if (lane == 0) scratch[w] = v;
    __syncthreads();
    if (threadIdx.x < 16) {
        v = scratch[threadIdx.x];
        #pragma unroll
        for (int o = 8; o > 0; o >>= 1) v = fmaxf(v, __shfl_down_sync(0xffffu, v, o, 16));
        if (threadIdx.x == 0) scratch[0] = v;
    }
    __syncthreads();
    float r = scratch[0];
    __syncthreads();
    return r;
}

// ---- prep: W1 = Wk @ Wa1 (split bf16, transposed) ; crel = rel@Wa3 + b_att ----
__global__ void __launch_bounds__(128) prep_kernel(
    const float* __restrict__ Wk, const float* __restrict__ W_att,
    const float* __restrict__ b_att, const float* __restrict__ rel)
{
    int blk = blockIdx.x;
    int t = threadIdx.x;
    if (blk == 0 && t == 0) g_count = 0;
    __shared__ float row_s[D];
    if (blk < D) {
        int k = blk;
        row_s[t] = Wk[k*D + t];
        __syncthreads();
        float acc = 0.f;
        #pragma unroll 8
        for (int j = 0; j < D; j++) acc += row_s[j] * W_att[j*D + t];
        __nv_bfloat16 hi = __float2bfloat16_rn(acc);
        __nv_bfloat16 lo = __float2bfloat16_rn(acc - __bfloat162float(hi));
        g_W1h[t*D + k] = hi;   // transposed: [d][k]
        g_W1l[t*D + k] = lo;
    } else {
        int b = blk - D;
        row_s[t] = rel[b*D + t];
        __syncthreads();
        float acc = b_att[t];
        #pragma unroll 8
        for (int j = 0; j < D; j++) acc += row_s[j] * W_att[(2*D + j)*D + t];
        g_crel[b*D + t] = acc;
    }
}

// ---- warp-aggregated compaction of active rows ----
__global__ void __launch_bounds__(256) compact_kernel(const int* __restrict__ mask) {
    int r = blockIdx.x * 256 + threadIdx.x;
    bool act = (mask[r] != 0);
    unsigned bal = __ballot_sync(0xffffffffu, act);
    int lane = threadIdx.x & 31;
    int tot = __popc(bal);
    int base = 0;
    if (lane == 0 && tot) base = atomicAdd(&g_count, tot);
    base = __shfl_sync(0xffffffffu, base, 0);
    if (act) g_idx[base + __popc(bal & ((1u << lane) - 1u))] = r;
}

// ---- tensor-core GEMM with ldmatrix loads ----
__device__ __forceinline__ void mma_bf16(float (&d)[4], const unsigned (&a)[4],
                                         const unsigned (&b)[2]) {
    asm volatile(
        "mma.sync.aligned.m16n8k16.row.col.f32.bf16.bf16.f32 "
        "{%0,%1,%2,%3}, {%4,%5,%6,%7}, {%8,%9}, {%0,%1,%2,%3};"
        : "+f"(d[0]), "+f"(d[1]), "+f"(d[2]), "+f"(d[3])
        : "r"(a[0]), "r"(a[1]), "r"(a[2]), "r"(a[3]), "r"(b[0]), "r"(b[1]));
}

#define LDSM_X4(r0,r1,r2,r3,addr) \
    asm volatile("ldmatrix.sync.aligned.m8n8.x4.shared.b16 {%0,%1,%2,%3}, [%4];" \
                 : "=r"(r0), "=r"(r1), "=r"(r2), "=r"(r3) : "r"(addr))

__global__ void __launch_bounds__(256) gemm_kernel(const float* __restrict__ key) {
    extern __shared__ char sh[];
    __nv_bfloat16* Ah = (__nv_bfloat16*)sh;          // [128][APAD]
    __nv_bfloat16* Al = Ah + 128*APAD;
    __nv_bfloat16* Bh = Al + 128*APAD;               // [d][APAD]
    __nv_bfloat16* Bl = Bh + 128*APAD;
    __shared__ int ridx[128];

    int cnt = g_count;
    int base = blockIdx.x * 128;
    if (base >= cnt) return;
    int tid = threadIdx.x;

    if (tid < 128) ridx[tid] = (base + tid < cnt) ? g_idx[base + tid] : -1;
    __syncthreads();

    // B: copy split W1 (bf16) into padded smem
    {
        unsigned* dBh = (unsigned*)Bh;
        unsigned* dBl = (unsigned*)Bl;
        const unsigned* sBh = (const unsigned*)g_W1h;
        const unsigned* sBl = (const unsigned*)g_W1l;
        for (int i = tid; i < D*D/2; i += 256) {
            int d = i >> 6, kp = i & 63;
            dBh[d*(APAD/2) + kp] = sBh[i];
            dBl[d*(APAD/2) + kp] = sBl[i];
        }
    }
    // A: load fp32 key rows, split into hi/lo bf16
    {
        int r = tid & 127, half = tid >> 7;
        int gr = ridx[r];
        const float* src = (gr >= 0) ? key + (size_t)gr * D + half*64 : (const float*)0;
        #pragma unroll
        for (int c = 0; c < 64; c += 4) {
            float4 v = src ? *(const float4*)(src + c)
                           : make_float4(0.f, 0.f, 0.f, 0.f);
            int col = half*64 + c;
            __nv_bfloat16 h0 = __float2bfloat16_rn(v.x);
            __nv_bfloat16 h1 = __float2bfloat16_rn(v.y);
            __nv_bfloat16 h2 = __float2bfloat16_rn(v.z);
            __nv_bfloat16 h3 = __float2bfloat16_rn(v.w);
            __nv_bfloat16 l0 = __float2bfloat16_rn(v.x - __bfloat162float(h0));
            __nv_bfloat16 l1 = __float2bfloat16_rn(v.y - __bfloat162float(h1));
            __nv_bfloat16 l2 = __float2bfloat16_rn(v.z - __bfloat162float(h2));
            __nv_bfloat16 l3 = __float2bfloat16_rn(v.w - __bfloat162float(h3));
            __nv_bfloat162* ph = (__nv_bfloat162*)(Ah + r*APAD + col);
            __nv_bfloat162* pl = (__nv_bfloat162*)(Al + r*APAD + col);
            ph[0] = __nv_bfloat162(h0, h1); ph[1] = __nv_bfloat162(h2, h3);
            pl[0] = __nv_bfloat162(l0, l1); pl[1] = __nv_bfloat162(l2, l3);
        }
    }
    __syncthreads();

    int w = tid >> 5, lane = tid & 31;
    int wr = w >> 1;        // warp rows [wr*32, +32)
    int wc = w & 1;         // warp cols [wc*64, +64)
    int grp = lane >> 2, q = lane & 3;

    // ldmatrix lane address components
    int a_row = lane & 15;                // tile-relative row
    int a_koff = (lane >> 4) * 8;         // k element offset (0 or 8)
    int b_row = (lane & 7) + ((lane >> 4) << 3);   // n-relative row (0-7 or 8-15)
    int b_koff = ((lane >> 3) & 1) * 8;            // k offset (0 or 8)

    unsigned uAh = (unsigned)__cvta_generic_to_shared(Ah);
    unsigned uAl = (unsigned)__cvta_generic_to_shared(Al);
    unsigned uBh = (unsigned)__cvta_generic_to_shared(Bh);
    unsigned uBl = (unsigned)__cvta_generic_to_shared(Bl);

    float acc[2][8][4];
    #pragma unroll
    for (int mt = 0; mt < 2; mt++)
        #pragma unroll
        for (int nt = 0; nt < 8; nt++)
            #pragma unroll
            for (int i = 0; i < 4; i++) acc[mt][nt][i] = 0.f;

    #pragma unroll
    for (int ks = 0; ks < 8; ks++) {
        int k0 = ks * 16;
        unsigned ah[2][4], al[2][4];
        #pragma unroll
        for (int mt = 0; mt < 2; mt++) {
            unsigned off = (unsigned)(((wr*32 + mt*16 + a_row)*APAD + k0 + a_koff) * 2);
            LDSM_X4(ah[mt][0], ah[mt][1], ah[mt][2], ah[mt][3], uAh + off);
            LDSM_X4(al[mt][0], al[mt][1], al[mt][2], al[mt][3], uAl + off);
        }
        unsigned bh[8][2], bl[8][2];
        #pragma unroll
        for (int p = 0; p < 4; p++) {     // each x4 covers 2 n-tiles
            unsigned off = (unsigned)(((wc*64 + p*16 + b_row)*APAD + k0 + b_koff) * 2);
            LDSM_X4(bh[2*p][0], bh[2*p][1], bh[2*p+1][0], bh[2*p+1][1], uBh + off);
            LDSM_X4(bl[2*p][0], bl[2*p][1], bl[2*p+1][0], bl[2*p+1][1], uBl + off);
        }
        #pragma unroll
        for (int mt = 0; mt < 2; mt++)
            #pragma unroll
            for (int nt = 0; nt < 8; nt++) {
                mma_bf16(acc[mt][nt], ah[mt], bh[nt]);
                mma_bf16(acc[mt][nt], ah[mt], bl[nt]);
                mma_bf16(acc[mt][nt], al[mt], bh[nt]);
            }
    }

    #pragma unroll
    for (int mt = 0; mt < 2; mt++) {
        int row = wr*32 + mt*16 + grp;
        int g1 = ridx[row], g2 = ridx[row + 8];
        #pragma unroll
        for (int nt = 0; nt < 8; nt++) {
            int col = wc*64 + nt*8 + q*2;
            if (g1 >= 0)
                *(float2*)(g_fkW + (size_t)g1 * D + col) =
                    make_float2(acc[mt][nt][0], acc[mt][nt][1]);
            if (g2 >= 0)
                *(float2*)(g_fkW + (size_t)g2 * D + col) =
                    make_float2(acc[mt][nt][2], acc[mt][nt][3]);
        }
    }
}

// ---- fused hop: per-b active-row compaction, unconditional streaming ----
__global__ void __launch_bounds__(512) hop_kernel(
    int hop,
    const float* __restrict__ e1,
    const float* __restrict__ value,
    const int*   __restrict__ mask,
    const float* __restrict__ W_att,
    const float* __restrict__ W_lin,
    const float* __restrict__ b_lin,
    const float* __restrict__ Wv,
    float* __restrict__ out)
{
    __shared__ __align__(16) float u_s[D];
    __shared__ __align__(16) float c_s[D];
    __shared__ float ub_s[D];
    __shared__ float att_s[NN];
    __shared__ unsigned short act_s[NN];
    __shared__ int wcnt[16];
    __shared__ int wbase[17];
    __shared__ float red_s[16*D];
    __shared__ float scratch[16];

    const float* u_in = (hop == 0) ? e1 : g_u;
    float* u_out = (hop == 2) ? out : g_u;

    int b = blockIdx.x;
    int tid = threadIdx.x;
    int lane = tid & 31, w = tid >> 5;   // 16 warps

    if (tid < D) u_s[tid] = u_in[b*D + tid];

    // per-b compaction of active n (one thread per n)
    {
        bool act = (mask[b*NN + tid] != 0);
        unsigned bal = __ballot_sync(0xffffffffu, act);
        if (lane == 0) wcnt[w] = __popc(bal);
        __syncthreads();
        if (tid == 0) {
            int s = 0;
            #pragma unroll
            for (int i = 0; i < 16; i++) { wbase[i] = s; s += wcnt[i]; }
            wbase[16] = s;
        }
        __syncthreads();
        if (act) {
            int pos = wbase[w] + __popc(bal & ((1u << lane) - 1u));
            act_s[pos] = (unsigned short)tid;
        }
    }
    int acnt = wbase[16];
    __syncthreads();

    // c = u@Wa2 + crel (threads 0..127); ub = lrelu(u@W_lin + b_lin) (128..255)
    if (tid < D) {
        int d = tid;
        float c = g_crel[b*D + d];
        #pragma unroll 8
        for (int k = 0; k < D; k++) c += u_s[k] * W_att[(D + k)*D + d];
        c_s[d] = c;
    } else if (tid < 2*D) {
        int d = tid - D;
        float v = b_lin[d];
        #pragma unroll 8
        for (int k = 0; k < D; k++) v += u_s[k] * W_lin[k*D + d];
        ub_s[d] = lrelu(v);
    }
    __syncthreads();

    // masked-row logit (exact: fk rows are 0 there)
    float att0 = block_sum512(tid < D ? lrelu(c_s[tid]) : 0.f, scratch);

    // pass 1: logits for active rows only (warp per row, 4-way unrolled)
    const float* fk_b = g_fkW + (size_t)b * NN * D;
    float4 cv = *(const float4*)&c_s[lane*4];
    for (int j0 = 0; j0 < acnt; j0 += 64) {
        float ss[4];
        int   ii_n[4];
        bool  vv[4];
        #pragma unroll
        for (int i = 0; i < 4; i++) {
            int idx = j0 + i*16 + w;
            vv[i] = (idx < acnt);
            ii_n[i] = vv[i] ? (int)act_s[idx] : 0;
            ss[i] = 0.f;
        }
        #pragma unroll
        for (int i = 0; i < 4; i++) if (vv[i]) {
            float4 v = *(const float4*)(fk_b + (size_t)ii_n[i]*D + lane*4);
            ss[i] = lrelu(v.x+cv.x) + lrelu(v.y+cv.y) + lrelu(v.z+cv.z) + lrelu(v.w+cv.w);
        }
        #pragma unroll
        for (int o = 16; o > 0; o >>= 1)
            #pragma unroll
            for (int i = 0; i < 4; i++)
                ss[i] += __shfl_down_sync(0xffffffffu, ss[i], o);
        if (lane == 0) {
            #pragma unroll
            for (int i = 0; i < 4; i++) {
                int idx = j0 + i*16 + w;
                if (idx < acnt) att_s[idx] = ss[i];
            }
        }
    }
    __syncthreads();

    // softmax over active logits; reference max includes masked logits (= att0)
    float mx = att0;
    for (int i = tid; i < acnt; i += 512) mx = fmaxf(mx, att_s[i]);
    mx = block_max512(mx, scratch);

    float Sp = 0.f;
    for (int i = tid; i < acnt; i += 512) {
        float e = expf(att_s[i] - mx);
        att_s[i] = e;
        Sp += e;
    }
    float S = block_sum512(Sp, scratch) + 1e-5f;

    // pass 2: q[d] = sum over active rows of e * value[b,n,d]
    const float* v_b = value + (size_t)b * NN * D;
    float o0 = 0.f, o1 = 0.f, o2 = 0.f, o3 = 0.f;
    for (int j0 = 0; j0 < acnt; j0 += 64) {
        #pragma unroll
        for (int i = 0; i < 4; i++) {
            int idx = j0 + i*16 + w;
            if (idx < acnt) {
                int n = (int)act_s[idx];
                float e = att_s[idx];
                float4 v = *(const float4*)(v_b + (size_t)n*D + lane*4);
                o0 += e*v.x; o1 += e*v.y; o2 += e*v.z; o3 += e*v.w;
            }
        }
    }
    red_s[w*D + lane*4 + 0] = o0;
    red_s[w*D + lane*4 + 1] = o1;
    red_s[w*D + lane*4 + 2] = o2;
    red_s[w*D + lane*4 + 3] = o3;
    __syncthreads();

    if (tid < D) {
        float o = 0.f;
        #pragma unroll
        for (int ww = 0; ww < 16; ww++) o += red_s[ww*D + tid];
        c_s[tid] = o / S;          // reuse c_s as q = p @ value
    }
    __syncthreads();

    if (tid < D) {
        float ov = 0.f;
        #pragma unroll 8
        for (int k = 0; k < D; k++) ov += c_s[k] * Wv[k*D + tid];
        u_s[tid] = ub_s[tid] + ov;  // pre-norm x
    }
    __syncthreads();

    float nrm2 = block_sum512(tid < D ? u_s[tid]*u_s[tid] : 0.f, scratch);
    float norm = sqrtf(nrm2);
    if (tid < D) {
        float x = u_s[tid];
        u_out[b*D + tid] = (norm > 1e-12f) ? (x / norm) : (x * 1e12f);
    }
}

extern "C" void kernel_launch(void* const* d_in, const int* in_sizes, int n_in,
                              void* d_out, int out_size) {
    const float* e1    = (const float*)d_in[0];
    const float* rel   = (const float*)d_in[1];
    const float* key   = (const float*)d_in[2];
    const float* value = (const float*)d_in[3];
    const int*   mask  = (const int*)  d_in[4];
    const float* Wk    = (const float*)d_in[5];
    const float* Wv    = (const float*)d_in[6];
    const float* Wlin  = (const float*)d_in[7];
    const float* blin  = (const float*)d_in[8];
    const float* Watt  = (const float*)d_in[9];
    const float* batt  = (const float*)d_in[10];
    float* out = (float*)d_out;

    prep_kernel<<<D + BB, 128>>>(Wk, Watt, batt, rel);
    compact_kernel<<<BN/256, 256>>>(mask);

    int gemm_smem = 4 * 128 * APAD * (int)sizeof(__nv_bfloat16);
    cudaFuncSetAttribute(gemm_kernel, cudaFuncAttributeMaxDynamicSharedMemorySize,
                         gemm_smem);
    gemm_kernel<<<BN/128, 256, gemm_smem>>>(key);

    for (int h = 0; h < 3; h++)
        hop_kernel<<<BB, 512>>>(h, e1, value, mask, Watt, Wlin, blin, Wv, out);
}